// round 2
// baseline (speedup 1.0000x reference)
#include <cuda_runtime.h>

#define BB 128
#define SS 512
#define KK 4
#define DD 300
#define CC 20
#define NN 10000
#define CHUNKS 8
#define SCHUNK (SS / CHUNKS)   // 64 s-positions per block
#define SGRP 16                // s-groups in accumulate phase
#define TPB (SGRP * CC)        // 320 threads
#define ROWS_PER_BLK 16        // node rows per block in P-build

// Scratch (deterministic, rewritten every call)
__device__ float g_P[NN * CC];               // P = node_emb @ fc_w^T   (800 KB)
__device__ float g_part[BB * CHUNKS * CC];   // per-(b,chunk) logit partials (80 KB)

// ---------------------------------------------------------------------------
// K1: P[n,c] = sum_d node_emb[n,d] * fc_w[c,d]
// ---------------------------------------------------------------------------
__global__ void __launch_bounds__(TPB) p_kernel(
    const float* __restrict__ node_emb, const float* __restrict__ fc_w)
{
    __shared__ float sE[ROWS_PER_BLK * DD];   // 18.75 KB
    __shared__ float sF[CC * DD];             // 24 KB

    const int t  = threadIdx.x;
    const int n0 = blockIdx.x * ROWS_PER_BLK;

    for (int i = t; i < ROWS_PER_BLK * DD; i += TPB) sE[i] = node_emb[n0 * DD + i];
    for (int i = t; i < CC * DD; i += TPB)           sF[i] = fc_w[i];
    __syncthreads();

    const int nl = t / CC, c = t % CC;
    const float* e = &sE[nl * DD];
    const float* f = &sF[c * DD];
    float acc = 0.f;
    #pragma unroll 4
    for (int d = 0; d < DD; d++) acc += e[d] * f[d];

    g_P[(n0 + nl) * CC + c] = acc;   // fully coalesced store
}

// ---------------------------------------------------------------------------
// K2: per-(b, s-chunk) logit partials via 80B gathers on P
// ---------------------------------------------------------------------------
__global__ void __launch_bounds__(TPB) gather_kernel(
    const int* __restrict__ X, const int* __restrict__ NX, const int* __restrict__ EW,
    const float* __restrict__ edge_w, const float* __restrict__ node_w)
{
    __shared__ int   sX[SCHUNK];
    __shared__ float sNW[SCHUNK];
    __shared__ int   sNX[SCHUNK * KK];
    __shared__ float sEW[SCHUNK * KK];
    __shared__ float sred[SGRP][CC];

    const int b  = blockIdx.y;
    const int ch = blockIdx.x;
    const int s0 = ch * SCHUNK;
    const int t  = threadIdx.x;

    // Phase 1: cooperative prefetch. 256 fully-random edge_w gathers issued
    // together -> one round of DRAM latency, high MLP.
    if (t < SCHUNK) {
        int x = X[b * SS + s0 + t];
        sX[t]  = x;
        sNW[t] = node_w[x];
    }
    for (int i = t; i < SCHUNK * KK; i += TPB) sNX[i] = NX[(b * SS + s0) * KK + i];
    for (int i = t; i < SCHUNK * KK; i += TPB) sEW[i] = edge_w[EW[(b * SS + s0) * KK + i]];
    __syncthreads();

    // Phase 2: thread (g, c) accumulates class c over its 4 s-positions.
    // Gathers hit the 800KB P table (L2/L1 resident), 80B per row group.
    const int g = t / CC, c = t % CC;
    float acc = 0.f;
    #pragma unroll
    for (int i = 0; i < SCHUNK / SGRP; i++) {
        const int s  = g + i * SGRP;
        const float nw = sNW[s];
        float m = 0.f;
        #pragma unroll
        for (int k = 0; k < KK; k++)
            m += sEW[s * KK + k] * __ldg(&g_P[sNX[s * KK + k] * CC + c]);
        acc += (1.f - nw) * m + nw * __ldg(&g_P[sX[s] * CC + c]);
    }
    sred[g][c] = acc;
    __syncthreads();

    // Fixed-order tree reduce over the 16 s-groups -> deterministic
    #pragma unroll
    for (int off = SGRP / 2; off > 0; off >>= 1) {
        if (g < off) sred[g][c] += sred[g + off][c];
        __syncthreads();
    }
    if (g == 0) g_part[(b * CHUNKS + ch) * CC + c] = sred[0][c];
}

// ---------------------------------------------------------------------------
// K3: reduce chunk partials, add bias, relu, softmax
// ---------------------------------------------------------------------------
__global__ void __launch_bounds__(32) head_kernel(
    const float* __restrict__ fc_b, float* __restrict__ out)
{
    const int b = blockIdx.x, t = threadIdx.x;

    float v = -1e30f, l = 0.f;
    if (t < CC) {
        float s = fc_b[t];
        #pragma unroll
        for (int ch = 0; ch < CHUNKS; ch++)
            s += g_part[(b * CHUNKS + ch) * CC + t];
        l = fmaxf(s, 0.f);   // relu
        v = l;
    }
    float mx = v;
    #pragma unroll
    for (int o = 16; o; o >>= 1) mx = fmaxf(mx, __shfl_xor_sync(0xffffffffu, mx, o));
    float e = (t < CC) ? __expf(l - mx) : 0.f;
    float sum = e;
    #pragma unroll
    for (int o = 16; o; o >>= 1) sum += __shfl_xor_sync(0xffffffffu, sum, o);
    if (t < CC) out[b * CC + t] = e / sum;
}

// ---------------------------------------------------------------------------
extern "C" void kernel_launch(void* const* d_in, const int* in_sizes, int n_in,
                              void* d_out, int out_size)
{
    const int*   X        = (const int*)  d_in[0];
    const int*   NX       = (const int*)  d_in[1];
    const int*   EW       = (const int*)  d_in[2];
    const float* node_emb = (const float*)d_in[3];
    const float* edge_w   = (const float*)d_in[4];
    const float* node_w   = (const float*)d_in[5];
    const float* fc_w     = (const float*)d_in[6];
    const float* fc_b     = (const float*)d_in[7];
    float* out = (float*)d_out;

    p_kernel<<<NN / ROWS_PER_BLK, TPB>>>(node_emb, fc_w);            // 625 blocks
    dim3 grid2(CHUNKS, BB);
    gather_kernel<<<grid2, TPB>>>(X, NX, EW, edge_w, node_w);        // 1024 blocks
    head_kernel<<<BB, 32>>>(fc_b, out);
}

// round 3
// speedup vs baseline: 1.4843x; 1.4843x over previous
#include <cuda_runtime.h>

#define BB 128
#define SS 512
#define KK 4
#define DD 300
#define CC 20
#define NN 10000
#define CHUNKS 8
#define SCHUNK (SS / CHUNKS)   // 64 s-positions per block
#define SGRP 16
#define TPB (SGRP * CC)        // 320 threads

// p_kernel tiling
#define PT_TPB   128
#define PT_NODES 64            // nodes per block (32 node-pairs x 4 class-groups)
#define PT_GRID  ((NN + PT_NODES - 1) / PT_NODES)   // 157

// Scratch (deterministic, rewritten every call)
__device__ float g_P[NN * CC];               // P = node_emb @ fc_w^T   (800 KB)
__device__ float g_part[BB * CHUNKS * CC];   // per-(b,chunk) logit partials

// ---------------------------------------------------------------------------
// K1: P[n,c] = sum_d node_emb[n,d] * fc_w[c,d]
// Register-tiled: thread = (node-pair, class-group of 5). node rows streamed
// from global via float4 (full L1-line reuse); fc_w broadcast from shared.
// Per d: 10 FFMA vs 5 LDS + 0.5 LDG.128  ->  FMA-bound, not smem-bound.
// ---------------------------------------------------------------------------
__global__ void __launch_bounds__(PT_TPB) p_kernel(
    const float* __restrict__ node_emb, const float* __restrict__ fc_w)
{
    __shared__ float sF[CC * DD];             // 24 KB

    const int t = threadIdx.x;
    for (int i = t; i < CC * DD; i += PT_TPB) sF[i] = fc_w[i];
    __syncthreads();

    const int ng = t >> 2;                    // 0..31 node-pair within block
    const int cg = t & 3;                     // 0..3  class-group (5 classes)
    const int n0 = blockIdx.x * PT_NODES + ng * 2;
    if (n0 >= NN) return;
    const int  n1    = (n0 + 1 < NN) ? n0 + 1 : n0;   // clamp; write guarded
    const bool has2  = (n0 + 1 < NN);

    const float4* __restrict__ e0 = (const float4*)(node_emb + (size_t)n0 * DD);
    const float4* __restrict__ e1 = (const float4*)(node_emb + (size_t)n1 * DD);
    const float*  __restrict__ f  = sF + cg * 5 * DD;

    float acc0[5] = {0.f, 0.f, 0.f, 0.f, 0.f};
    float acc1[5] = {0.f, 0.f, 0.f, 0.f, 0.f};

    #pragma unroll 5
    for (int dq = 0; dq < DD / 4; dq++) {     // 75 iters, 4 d's each
        const float4 a0 = e0[dq];
        const float4 a1 = e1[dq];
        const int d = dq * 4;
        #pragma unroll
        for (int j = 0; j < 4; j++) {
            const float ev0 = (&a0.x)[j];
            const float ev1 = (&a1.x)[j];
            #pragma unroll
            for (int c5 = 0; c5 < 5; c5++) {
                const float fv = f[c5 * DD + d + j];
                acc0[c5] += ev0 * fv;
                acc1[c5] += ev1 * fv;
            }
        }
    }

    #pragma unroll
    for (int c5 = 0; c5 < 5; c5++) {
        g_P[n0 * CC + cg * 5 + c5] = acc0[c5];
        if (has2) g_P[(n0 + 1) * CC + cg * 5 + c5] = acc1[c5];
    }
}

// ---------------------------------------------------------------------------
// K2: per-(b, s-chunk) logit partials via 80B gathers on P
// ---------------------------------------------------------------------------
__global__ void __launch_bounds__(TPB) gather_kernel(
    const int* __restrict__ X, const int* __restrict__ NX, const int* __restrict__ EW,
    const float* __restrict__ edge_w, const float* __restrict__ node_w)
{
    __shared__ int   sX[SCHUNK];
    __shared__ float sNW[SCHUNK];
    __shared__ int   sNX[SCHUNK * KK];
    __shared__ float sEW[SCHUNK * KK];
    __shared__ float sred[SGRP][CC];

    const int b  = blockIdx.y;
    const int ch = blockIdx.x;
    const int s0 = ch * SCHUNK;
    const int t  = threadIdx.x;

    if (t < SCHUNK) {
        int x = X[b * SS + s0 + t];
        sX[t]  = x;
        sNW[t] = node_w[x];
    }
    for (int i = t; i < SCHUNK * KK; i += TPB) sNX[i] = NX[(b * SS + s0) * KK + i];
    for (int i = t; i < SCHUNK * KK; i += TPB) sEW[i] = edge_w[EW[(b * SS + s0) * KK + i]];
    __syncthreads();

    const int g = t / CC, c = t % CC;
    float acc = 0.f;
    #pragma unroll
    for (int i = 0; i < SCHUNK / SGRP; i++) {
        const int s  = g + i * SGRP;
        const float nw = sNW[s];
        float m = 0.f;
        #pragma unroll
        for (int k = 0; k < KK; k++)
            m += sEW[s * KK + k] * __ldg(&g_P[sNX[s * KK + k] * CC + c]);
        acc += (1.f - nw) * m + nw * __ldg(&g_P[sX[s] * CC + c]);
    }
    sred[g][c] = acc;
    __syncthreads();

    #pragma unroll
    for (int off = SGRP / 2; off > 0; off >>= 1) {
        if (g < off) sred[g][c] += sred[g + off][c];
        __syncthreads();
    }
    if (g == 0) g_part[(b * CHUNKS + ch) * CC + c] = sred[0][c];
}

// ---------------------------------------------------------------------------
// K3: reduce chunk partials, add bias, relu, softmax
// ---------------------------------------------------------------------------
__global__ void __launch_bounds__(32) head_kernel(
    const float* __restrict__ fc_b, float* __restrict__ out)
{
    const int b = blockIdx.x, t = threadIdx.x;

    float v = -1e30f, l = 0.f;
    if (t < CC) {
        float s = fc_b[t];
        #pragma unroll
        for (int ch = 0; ch < CHUNKS; ch++)
            s += g_part[(b * CHUNKS + ch) * CC + t];
        l = fmaxf(s, 0.f);
        v = l;
    }
    float mx = v;
    #pragma unroll
    for (int o = 16; o; o >>= 1) mx = fmaxf(mx, __shfl_xor_sync(0xffffffffu, mx, o));
    float e = (t < CC) ? __expf(l - mx) : 0.f;
    float sum = e;
    #pragma unroll
    for (int o = 16; o; o >>= 1) sum += __shfl_xor_sync(0xffffffffu, sum, o);
    if (t < CC) out[b * CC + t] = e / sum;
}

// ---------------------------------------------------------------------------
extern "C" void kernel_launch(void* const* d_in, const int* in_sizes, int n_in,
                              void* d_out, int out_size)
{
    const int*   X        = (const int*)  d_in[0];
    const int*   NX       = (const int*)  d_in[1];
    const int*   EW       = (const int*)  d_in[2];
    const float* node_emb = (const float*)d_in[3];
    const float* edge_w   = (const float*)d_in[4];
    const float* node_w   = (const float*)d_in[5];
    const float* fc_w     = (const float*)d_in[6];
    const float* fc_b     = (const float*)d_in[7];
    float* out = (float*)d_out;

    p_kernel<<<PT_GRID, PT_TPB>>>(node_emb, fc_w);
    dim3 grid2(CHUNKS, BB);
    gather_kernel<<<grid2, TPB>>>(X, NX, EW, edge_w, node_w);
    head_kernel<<<BB, 32>>>(fc_b, out);
}